// round 17
// baseline (speedup 1.0000x reference)
#include <cuda_runtime.h>
#include <cuda_fp16.h>
#include <cstdint>
#include <math.h>

#define T_SEQ 512
#define B_    64
#define H_    1024
#define G_    3072
#define L_    3
#define NBLK  128
#define CLS   4
#define NGRP  32
#define KPB   256

// recur dynamic SMEM (words):
//   hs[64][132] fp16x2 staging, sc[64][100] local merge, pi[64][4][26] push inbox
#define HS_W   132
#define SC_OFF (64 * HS_W)          // 8448
#define SC_W   100
#define PI_OFF (SC_OFF + 64 * SC_W) // 14848
#define PI_W   26                   // slot stride (even -> 8B-aligned pairs)
#define SMEMB_R ((PI_OFF + 64 * 4 * PI_W) * 4)   // 86016 B

// gx dynamic SMEM: 3-stage, A 3x(128x72) halfs + B 3x(128x72) halfs
#define GX_STG   9216
#define GX_NSTG  3
#define GX_SMEM  (2 * GX_NSTG * GX_STG * 2)      // 110592 B
#define GX_NK    16

__device__ float  g_gx[(size_t)T_SEQ * B_ * G_];
__device__ __half g_xh[(size_t)T_SEQ * B_ * H_];
__device__ __half g_wih[(size_t)L_ * G_ * H_];
__device__ __half g_h0h[(size_t)L_ * B_ * H_];
__device__ __half g_seqhA[(size_t)T_SEQ * B_ * H_];
__device__ __half g_seqhB[(size_t)T_SEQ * B_ * H_];
__device__ unsigned g_cnt[NGRP];

extern __shared__ unsigned sh[];

__device__ __forceinline__ unsigned f2h2(float lo, float hi) {
    __half2 h = __floats2half2_rn(lo, hi);
    return *(unsigned*)&h;
}

__device__ __forceinline__ void mma_f16(float* c, const unsigned* a, const unsigned* b) {
    asm volatile(
        "mma.sync.aligned.m16n8k16.row.col.f32.f16.f16.f32 "
        "{%0,%1,%2,%3}, {%4,%5,%6,%7}, {%8,%9}, {%0,%1,%2,%3};"
        : "+f"(c[0]), "+f"(c[1]), "+f"(c[2]), "+f"(c[3])
        : "r"(a[0]), "r"(a[1]), "r"(a[2]), "r"(a[3]), "r"(b[0]), "r"(b[1]));
}

__device__ __forceinline__ void ldsm4(unsigned* r, uint32_t addr) {
    asm volatile("ldmatrix.sync.aligned.m8n8.x4.shared.b16 {%0,%1,%2,%3}, [%4];"
                 : "=r"(r[0]), "=r"(r[1]), "=r"(r[2]), "=r"(r[3]) : "r"(addr));
}

__device__ __forceinline__ void cpa16(uint32_t dst, const void* src) {
    asm volatile("cp.async.cg.shared.global [%0], [%1], 16;" :: "r"(dst), "l"(src));
}

__global__ void reset_cnt() { if (threadIdx.x < NGRP) g_cnt[threadIdx.x] = 0u; }

__global__ void tohalf(const float* __restrict__ s, int dstsel, int n8) {
    int i = blockIdx.x * 256 + threadIdx.x;
    if (i >= n8) return;
    __half* d = (dstsel == 0) ? g_xh : (dstsel == 1 ? g_wih : g_h0h);
    float4 a = *(const float4*)(s + (size_t)i * 8);
    float4 b = *(const float4*)(s + (size_t)i * 8 + 4);
    uint4 u = make_uint4(f2h2(a.x, a.y), f2h2(a.z, a.w), f2h2(b.x, b.y), f2h2(b.z, b.w));
    *(uint4*)(d + (size_t)i * 8) = u;
}

__device__ __forceinline__ uint32_t s2u(const void* p) {
    uint32_t a;
    asm("{ .reg .u64 t; cvta.to.shared.u64 t, %1; cvt.u32.u64 %0, t; }" : "=r"(a) : "l"(p));
    return a;
}

// ---------------- input-gate GEMM: fp16, cp.async 3-stage, ldmatrix ----------------
__global__ void __launch_bounds__(256, 2) gx_gemm(int sel,
    const __half* __restrict__ Wbase, const float* __restrict__ bias)
{
    const __half* A = (sel == 0) ? g_xh : (sel == 1 ? g_seqhA : g_seqhB);
    const __half* W = Wbase;
    float* out = g_gx;

    const uint32_t smb = s2u(sh);
    const int tid = threadIdx.x, lane = tid & 31, warp = tid >> 5;
    const int mbase = blockIdx.y * 128, nbase = blockIdx.x * 128;
    const int wm = (warp >> 2) * 64;
    const int wn = (warp & 3) * 32;
    const int q = lane & 3, g8 = lane >> 2;

    const int a_off = (wm + (lane & 15)) * 144 + (lane >> 4) * 16;
    const int mm = lane >> 3;
    const int b_off = (wn + (mm >> 1) * 8 + (lane & 7)) * 144 + (mm & 1) * 16;

    int arow[4], aseg[4];
#pragma unroll
    for (int i = 0; i < 4; i++) {
        int id = tid + i * 256;
        arow[i] = id >> 3; aseg[i] = id & 7;
    }

    float acc[4][4][4];
#pragma unroll
    for (int i = 0; i < 4; i++)
#pragma unroll
        for (int j = 0; j < 4; j++)
#pragma unroll
            for (int k = 0; k < 4; k++) acc[i][j][k] = 0.f;

#define GX_STAGE(s, kt)                                                           \
    do {                                                                          \
        _Pragma("unroll")                                                         \
        for (int i = 0; i < 4; i++) {                                             \
            uint32_t dst = smb + ((s) * GX_STG + arow[i] * 72 + aseg[i] * 8) * 2; \
            cpa16(dst, A + (size_t)(mbase + arow[i]) * H_ + (kt) * 64 + aseg[i] * 8); \
        }                                                                         \
        _Pragma("unroll")                                                         \
        for (int i = 0; i < 4; i++) {                                             \
            uint32_t dst = smb + ((GX_NSTG + (s)) * GX_STG + arow[i] * 72 + aseg[i] * 8) * 2; \
            cpa16(dst, W + (size_t)(nbase + arow[i]) * H_ + (kt) * 64 + aseg[i] * 8);  \
        }                                                                         \
        asm volatile("cp.async.commit_group;" ::: "memory");                      \
    } while (0)

    GX_STAGE(0, 0);
    GX_STAGE(1, 1);

    for (int kt = 0; kt < GX_NK; kt++) {
        if (kt + 2 < GX_NK) {
            GX_STAGE((kt + 2) % GX_NSTG, kt + 2);
            asm volatile("cp.async.wait_group 2;" ::: "memory");
        } else if (kt + 1 < GX_NK) {
            asm volatile("cp.async.wait_group 1;" ::: "memory");
        } else {
            asm volatile("cp.async.wait_group 0;" ::: "memory");
        }
        __syncthreads();

        const int s = kt % GX_NSTG;
        const uint32_t abase = smb + s * GX_STG * 2 + a_off;
        const uint32_t bbase = smb + (GX_NSTG + s) * GX_STG * 2 + b_off;
#pragma unroll
        for (int kc = 0; kc < 4; kc++) {
            unsigned a[4][4], b[2][4];
#pragma unroll
            for (int mi = 0; mi < 4; mi++)
                ldsm4(a[mi], abase + mi * 16 * 144 + kc * 32);
#pragma unroll
            for (int n2 = 0; n2 < 2; n2++)
                ldsm4(b[n2], bbase + n2 * 16 * 144 + kc * 32);
#pragma unroll
            for (int mi = 0; mi < 4; mi++)
#pragma unroll
                for (int ni = 0; ni < 4; ni++)
                    mma_f16(acc[mi][ni], a[mi], &b[ni >> 1][(ni & 1) * 2]);
        }
        __syncthreads();
    }

#pragma unroll
    for (int mi = 0; mi < 4; mi++) {
        int m = mbase + wm + mi * 16 + g8;
#pragma unroll
        for (int ni = 0; ni < 4; ni++) {
            int n = nbase + wn + ni * 8 + 2 * q;
            float b0 = bias[n], b1 = bias[n + 1];
            *(float2*)(out + (size_t)m * G_ + n) =
                make_float2(acc[mi][ni][0] + b0, acc[mi][ni][1] + b1);
            *(float2*)(out + (size_t)(m + 8) * G_ + n) =
                make_float2(acc[mi][ni][2] + b0, acc[mi][ni][3] + b1);
        }
    }
#undef GX_STAGE
}

// ---------------- persistent recurrence: push-based DSMEM exchange ----------------
__global__ void __launch_bounds__(256, 1) __cluster_dims__(CLS, 1, 1) recur(
    const float* __restrict__ Whh, const float* __restrict__ bhh,
    const float* __restrict__ h0, const __half* __restrict__ h0h,
    int outsel, float* __restrict__ hlast, unsigned cbase)
{
    unsigned (*hs)[HS_W] = (unsigned(*)[HS_W])sh;
    float    (*sc)[SC_W] = (float(*)[SC_W])(sh + SC_OFF);
    float*   pi          = (float*)(sh + PI_OFF);     // [64][4][PI_W]
    __half* seqh = outsel ? g_seqhB : g_seqhA;

    const int tid = threadIdx.x, blk = blockIdx.x;
    const int grp = blk >> 2;
    const uint32_t rank = blk & 3;
    const int lane = tid & 31, warp = tid >> 5;
    const int q = lane & 3, g8 = lane >> 2;
    const int wq = warp & 3;
    const int kh = warp >> 2;

    const uint32_t hs_base = s2u(&hs[0][0]);
    const uint32_t pi_base = s2u(pi);

    // per-thread gate indices + loop-invariant biases + register hold state
    int b_o[2], ghid_o[2], j_o[2];
    float br_o[2], bz_o[2], bn_o[2], hold[2];
#pragma unroll
    for (int o = 0; o < 2; o++) {
        int oi = tid + o * 256;
        b_o[o] = oi >> 3;
        j_o[o] = oi & 7;                          // unit within my 8-unit band
        int ghid = grp * 32 + (int)rank * 8 + j_o[o];
        ghid_o[o] = ghid;
        br_o[o] = bhh[ghid];
        bz_o[o] = bhh[H_ + ghid];
        bn_o[o] = bhh[2 * H_ + ghid];
        hold[o] = h0[(size_t)b_o[o] * H_ + ghid];
    }

    // W_hh fragments in registers (fp16x2), once per layer
    unsigned wreg[8][3][2];
#pragma unroll
    for (int kc = 0; kc < 8; kc++)
#pragma unroll
        for (int ni = 0; ni < 3; ni++) {
            int col = wq * 24 + ni * 8 + g8;
            int wrow = (col >> 5) * H_ + grp * 32 + (col & 31);
            size_t base = (size_t)wrow * H_ + rank * KPB + kh * 128 + kc * 16;
            wreg[kc][ni][0] = f2h2(Whh[base + 2 * q],     Whh[base + 2 * q + 1]);
            wreg[kc][ni][1] = f2h2(Whh[base + 2 * q + 8], Whh[base + 2 * q + 9]);
        }

    for (int t = 0; t < T_SEQ; t++) {
        // ---- dataflow wait: my 8 producer groups finished step t-1 ----
        if (t > 0) {
            if (warp == 0 && lane < 8) {
                const unsigned tgt = cbase + 4u * (unsigned)t;
                const unsigned* cp = &g_cnt[rank * 8 + lane];
                unsigned v;
                do {
                    asm volatile("ld.acquire.gpu.u32 %0, [%1];" : "=r"(v) : "l"(cp) : "memory");
                } while (v < tgt);
            }
            __syncthreads();
        }

        // ---- stage h slice [64 x 256] fp16 via cp.async ----
        {
            const __half* hstage = (t == 0) ? h0h : (seqh + (size_t)(t - 1) * B_ * H_);
            const __half* src = hstage + rank * KPB;
#pragma unroll
            for (int i = 0; i < 8; i++) {
                int id = tid + i * 256;
                int r = id >> 5, c16 = id & 31;
                uint32_t dst = hs_base + (uint32_t)(r * (HS_W * 4) + c16 * 16);
                cpa16(dst, src + (size_t)r * H_ + c16 * 8);
            }
            asm volatile("cp.async.commit_group;" ::: "memory");
            asm volatile("cp.async.wait_group 0;" ::: "memory");
        }
        __syncthreads();

        // ---- prefetch gate inputs (fly during GEMM) ----
        float xr[2], xz[2], xn[2];
#pragma unroll
        for (int o = 0; o < 2; o++) {
            const float* gxt = g_gx + ((size_t)t * B_ + b_o[o]) * G_;
            xr[o] = __ldcg(gxt + ghid_o[o]);
            xz[o] = __ldcg(gxt + H_ + ghid_o[o]);
            xn[o] = __ldcg(gxt + 2 * H_ + ghid_o[o]);
        }

        // ---- GEMM: each warp 64Mx24Nx128K, fp16, B from registers ----
        float acc[4][3][4];
#pragma unroll
        for (int mi = 0; mi < 4; mi++)
#pragma unroll
            for (int ni = 0; ni < 3; ni++)
#pragma unroll
                for (int k = 0; k < 4; k++) acc[mi][ni][k] = 0.f;

#pragma unroll
        for (int kc = 0; kc < 8; kc++) {
            int kb2 = kh * 64 + kc * 8;
            unsigned a[4][4];
#pragma unroll
            for (int mi = 0; mi < 4; mi++) {
                int m0 = mi * 16 + g8;
                a[mi][0] = hs[m0][kb2 + q];
                a[mi][1] = hs[m0 + 8][kb2 + q];
                a[mi][2] = hs[m0][kb2 + q + 4];
                a[mi][3] = hs[m0 + 8][kb2 + q + 4];
            }
#pragma unroll
            for (int mi = 0; mi < 4; mi++)
#pragma unroll
                for (int ni = 0; ni < 3; ni++)
                    mma_f16(acc[mi][ni], a[mi], wreg[kc][ni]);
        }

        // W2: peers' local reads of previous step's inbox done (pairs with A2 of t-1)
        if (t > 0)
            asm volatile("barrier.cluster.wait.aligned;" ::: "memory");

        // local kh-merge into sc
        if (kh == 1) {
#pragma unroll
            for (int mi = 0; mi < 4; mi++)
#pragma unroll
                for (int ni = 0; ni < 3; ni++) {
                    int n = wq * 24 + ni * 8 + 2 * q;
                    int m0 = mi * 16 + g8;
                    sc[m0][n] = acc[mi][ni][0];     sc[m0][n + 1] = acc[mi][ni][1];
                    sc[m0 + 8][n] = acc[mi][ni][2]; sc[m0 + 8][n + 1] = acc[mi][ni][3];
                }
        }
        __syncthreads();
        if (kh == 0) {
#pragma unroll
            for (int mi = 0; mi < 4; mi++)
#pragma unroll
                for (int ni = 0; ni < 3; ni++) {
                    int n = wq * 24 + ni * 8 + 2 * q;
                    int m0 = mi * 16 + g8;
                    sc[m0][n] += acc[mi][ni][0];     sc[m0][n + 1] += acc[mi][ni][1];
                    sc[m0 + 8][n] += acc[mi][ni][2]; sc[m0 + 8][n + 1] += acc[mi][ni][3];
                }
        }
        __syncthreads();

        // ---- push merged partials into destination ranks' inboxes ----
        // sc[m][n]: n = gate*32 + unit ; dst rank = unit/8 ; j = gate*8 + unit%8
        // inbox slot at dst: pi[(m*4 + myrank)*PI_W + j]
        // 3072 pairs total, 256 threads, 12 iterations of stride 256 (FIX: was 6 x 512)
#pragma unroll
        for (int i = 0; i < 12; i++) {
            int id = tid + i * 256;          // 0..3071 = 64 m x 48 pairs
            int m = id / 48;
            int p = id - m * 48;
            int n = 2 * p;
            uint32_t dstr = (uint32_t)((n & 31) >> 3);
            int j = ((n >> 5) << 3) + (n & 7);
            float v0 = sc[m][n], v1 = sc[m][n + 1];
            uint32_t la = pi_base + (uint32_t)(((m * 4 + (int)rank) * PI_W + j) * 4);
            uint32_t ra;
            asm("mapa.shared::cluster.u32 %0, %1, %2;" : "=r"(ra) : "r"(la), "r"(dstr));
            asm volatile("st.shared::cluster.f32 [%0], %1;" :: "r"(ra), "f"(v0) : "memory");
            asm volatile("st.shared::cluster.f32 [%0+4], %1;" :: "r"(ra), "f"(v1) : "memory");
        }

        // A1 + W1: all pushes visible in every rank's inbox
        asm volatile("barrier.cluster.arrive.aligned;" ::: "memory");
        asm volatile("barrier.cluster.wait.aligned;" ::: "memory");

        // ---- fused reduction (local reads) + gates ----
#pragma unroll
        for (int o = 0; o < 2; o++) {
            float sr = 0.f, sz = 0.f, sn = 0.f;
#pragma unroll
            for (int r = 0; r < CLS; r++) {
                const float* row = pi + (b_o[o] * 4 + r) * PI_W;
                sr += row[j_o[o]];
                sz += row[8 + j_o[o]];
                sn += row[16 + j_o[o]];
            }

            float rr = 1.f / (1.f + expf(-(xr[o] + sr + br_o[o])));
            float zz = 1.f / (1.f + expf(-(xz[o] + sz + bz_o[o])));
            float nn = tanhf(xn[o] + rr * (sn + bn_o[o]));
            float hv = (1.f - zz) * nn + zz * hold[o];
            hold[o] = hv;

            seqh[((size_t)t * B_ + b_o[o]) * H_ + ghid_o[o]] = __float2half_rn(hv);
            if (t == T_SEQ - 1)
                hlast[(size_t)b_o[o] * H_ + ghid_o[o]] = hv;
        }

        // A2: my inbox reads done (matched by W2 of t+1)
        asm volatile("barrier.cluster.arrive.aligned;" ::: "memory");

        // publish: seqh writes for step t visible -> bump my group's counter
        __syncthreads();
        if (tid == 0)
            asm volatile("red.release.gpu.add.u32 [%0], %1;"
                         :: "l"(&g_cnt[grp]), "r"(1u) : "memory");
    }

    asm volatile("barrier.cluster.wait.aligned;" ::: "memory");
}

extern "C" void kernel_launch(void* const* d_in, const int* in_sizes, int n_in,
                              void* d_out, int out_size)
{
    const float* x   = (const float*)d_in[0];
    const float* h0  = (const float*)d_in[1];
    const float* Wih = (const float*)d_in[2];
    const float* Whh = (const float*)d_in[3];
    const float* bih = (const float*)d_in[4];
    const float* bhh = (const float*)d_in[5];
    float* out = (float*)d_out;

    cudaFuncSetAttribute(recur, cudaFuncAttributeMaxDynamicSharedMemorySize, SMEMB_R);
    cudaFuncSetAttribute(gx_gemm, cudaFuncAttributeMaxDynamicSharedMemorySize, GX_SMEM);

    {
        int n8x = (int)((size_t)T_SEQ * B_ * H_ / 8);
        int n8w = (int)((size_t)L_ * G_ * H_ / 8);
        int n8h = (int)((size_t)L_ * B_ * H_ / 8);
        tohalf<<<(n8x + 255) / 256, 256>>>(x, 0, n8x);
        tohalf<<<(n8w + 255) / 256, 256>>>(Wih, 1, n8w);
        tohalf<<<(n8h + 255) / 256, 256>>>(h0, 2, n8h);
        reset_cnt<<<1, 32>>>();
    }

    __half* wih_dev = nullptr;
    __half* h0h_dev = nullptr;
    cudaGetSymbolAddress((void**)&wih_dev, g_wih);
    cudaGetSymbolAddress((void**)&h0h_dev, g_h0h);

    dim3 ggrid(G_ / 128, (T_SEQ * B_) / 128);
    for (int l = 0; l < L_; l++) {
        gx_gemm<<<ggrid, 256, GX_SMEM>>>(l == 0 ? 0 : (l == 1 ? 1 : 2),
                                         wih_dev + (size_t)l * G_ * H_,
                                         bih + (size_t)l * G_);
        recur<<<NBLK, 256, SMEMB_R>>>(Whh + (size_t)l * G_ * H_,
                                      bhh + (size_t)l * G_,
                                      h0 + (size_t)l * B_ * H_,
                                      h0h_dev + (size_t)l * B_ * H_,
                                      l & 1 ? 1 : 0,
                                      out + (size_t)l * B_ * H_,
                                      (unsigned)(l * 4 * T_SEQ));
    }
}